// round 10
// baseline (speedup 1.0000x reference)
#include <cuda_runtime.h>
#include <cuda_bf16.h>
#include <cstdint>

// Problem constants: B=4, H=64, W=64, C=64, GROUPS=8
#define BATCH 4
#define GROUPS 8
#define SEQ 4096
#define NTOK (BATCH * SEQ)
#define GN_EPS 1e-5f
#define SCALE 0.125f
#define LOG2E 1.4426950408889634f

// ---------------- scratch ---------------------------------------------------
__device__ float g_xn[NTOK * 64];                        // fp32 [b][t][c]
__device__ __nv_bfloat16 g_qb[NTOK * 64];                // bf16 [b][t][d] (pre-scaled)
__device__ __nv_bfloat16 g_kb[NTOK * 64];                // bf16 [b][t][d]
__device__ __nv_bfloat16 g_vtb[BATCH * 64 * SEQ];        // bf16 [b][d][t]
__device__ __nv_bfloat16 g_woT[64 * 64];                 // bf16 [out][in]
__device__ float g_po[2 * NTOK * 64];                    // partial O (unnormalized)
__device__ float g_pl[2 * NTOK];                         // partial row sums

// ---------------- PTX helpers ----------------------------------------------
#define LDSM4(r0, r1, r2, r3, addr)                                          \
    asm volatile("ldmatrix.sync.aligned.m8n8.x4.shared.b16 {%0,%1,%2,%3}, [%4];" \
                 : "=r"(r0), "=r"(r1), "=r"(r2), "=r"(r3) : "r"(addr))

#define MMA16816(d, a0, a1, a2, a3, b0, b1)                                  \
    asm volatile("mma.sync.aligned.m16n8k16.row.col.f32.bf16.bf16.f32 "      \
                 "{%0,%1,%2,%3}, {%4,%5,%6,%7}, {%8,%9}, {%0,%1,%2,%3};"     \
                 : "+f"(d[0]), "+f"(d[1]), "+f"(d[2]), "+f"(d[3])            \
                 : "r"(a0), "r"(a1), "r"(a2), "r"(a3), "r"(b0), "r"(b1))

#define CP_ASYNC16(dst, src)                                                 \
    asm volatile("cp.async.cg.shared.global [%0], [%1], 16;"                 \
                 :: "r"(dst), "l"(src))
#define CP_COMMIT()  asm volatile("cp.async.commit_group;")
#define CP_WAIT1()   asm volatile("cp.async.wait_group 1;")

__device__ __forceinline__ unsigned pk2(float hi, float lo) {
    unsigned d;
    asm("cvt.rn.bf16x2.f32 %0, %1, %2;" : "=r"(d) : "f"(hi), "f"(lo));
    return d;
}
__device__ __forceinline__ float ex2(float x) {
    float r;
    asm("ex2.approx.f32 %0, %1;" : "=f"(r) : "f"(x));
    return r;
}

// ---------------- kernel 1: fused GN stats + xn + Q/K/V (+WoT) --------------
__global__ void __launch_bounds__(256) gn_qkv_kernel(
    const float* __restrict__ x,
    const float* __restrict__ gamma, const float* __restrict__ beta,
    const float* __restrict__ Wq, const float* __restrict__ bq,
    const float* __restrict__ Wk, const float* __restrict__ bk,
    const float* __restrict__ Wv, const float* __restrict__ bv,
    const float* __restrict__ Wo)
{
    __shared__ float xs[64 * 65];
    __shared__ float ws[64 * 64];

    int blk = blockIdx.x;             // b*64 + h
    int b = blk >> 6, h = blk & 63, gg = h >> 3;
    int tid = threadIdx.x;

    const float4* gp = (const float4*)(x + (size_t)(b * 64 + gg * 8) * 4096);
    float s = 0.f, s2 = 0.f;
    #pragma unroll 8
    for (int i = tid; i < 8192; i += 256) {
        float4 v = gp[i];
        s  += v.x + v.y + v.z + v.w;
        s2 += v.x * v.x + v.y * v.y + v.z * v.z + v.w * v.w;
    }
    float* sh1 = ws;
    float* sh2 = ws + 256;
    sh1[tid] = s; sh2[tid] = s2;
    __syncthreads();
    for (int st = 128; st > 0; st >>= 1) {
        if (tid < st) { sh1[tid] += sh1[tid + st]; sh2[tid] += sh2[tid + st]; }
        __syncthreads();
    }
    if (tid == 0) {
        float mean = sh1[0] * (1.f / 32768.f);
        float var  = sh2[0] * (1.f / 32768.f) - mean * mean;
        xs[0] = mean;
        xs[1] = rsqrtf(var + GN_EPS);
    }
    __syncthreads();
    float mean = xs[0], rstd = xs[1];
    __syncthreads();

    float a  = rstd * gamma[h];
    float c0 = beta[h] - mean * a;

    const float4* xp  = (const float4*)(x + (size_t)blk * 4096);
    float4*       xng = (float4*)(g_xn + (size_t)blk * 4096);

    for (int r = 0; r < 4; r++) {
        int i4 = tid + r * 256;
        float4 v = xp[i4];
        v.x = v.x * a + c0; v.y = v.y * a + c0;
        v.z = v.z * a + c0; v.w = v.w * a + c0;
        xng[i4] = v;
        int e = i4 * 4, w = e >> 6, c = e & 63;
        xs[w * 65 + c + 0] = v.x; xs[w * 65 + c + 1] = v.y;
        xs[w * 65 + c + 2] = v.z; xs[w * 65 + c + 3] = v.w;
    }
    __syncthreads();

    const float SC2 = SCALE * LOG2E;

    for (int mtx = 0; mtx < 2; mtx++) {
        const float* Wm = mtx ? Wk : Wq;
        const float* bm = mtx ? bk : bq;
        __nv_bfloat16* og = mtx ? g_kb : g_qb;
        float qs = mtx ? 1.f : SC2;
        for (int r = 0; r < 4; r++)
            ((float4*)ws)[tid + r * 256] = ((const float4*)Wm)[tid + r * 256];
        __syncthreads();

        int c = tid & 63, wb = tid >> 6;
        float acc[16];
        #pragma unroll
        for (int i = 0; i < 16; i++) acc[i] = 0.f;
        for (int j = 0; j < 64; j++) {
            float wv = ws[j * 64 + c];
            #pragma unroll
            for (int i = 0; i < 16; i++)
                acc[i] += xs[(wb * 16 + i) * 65 + j] * wv;
        }
        float bb = bm[c];
        #pragma unroll
        for (int i = 0; i < 16; i++)
            og[((size_t)b * 4096 + h * 64 + wb * 16 + i) * 64 + c] =
                __float2bfloat16((acc[i] + bb) * qs);
        __syncthreads();
    }

    for (int r = 0; r < 4; r++)
        ((float4*)ws)[tid + r * 256] = ((const float4*)Wv)[tid + r * 256];
    __syncthreads();
    {
        int w = tid & 63, cb = tid >> 6;
        float acc[16];
        #pragma unroll
        for (int c = 0; c < 16; c++) acc[c] = 0.f;
        for (int j = 0; j < 64; j++) {
            float xv = xs[w * 65 + j];
            const float* wr = ws + j * 64 + cb * 16;
            #pragma unroll
            for (int c = 0; c < 16; c++) acc[c] += xv * wr[c];
        }
        #pragma unroll
        for (int c = 0; c < 16; c++) {
            int cc = cb * 16 + c;
            g_vtb[(size_t)(b * 64 + cc) * 4096 + h * 64 + w] =
                __float2bfloat16(acc[c] + bv[cc]);
        }
    }

    if (blk == 0) {
        for (int i = tid; i < 4096; i += 256) {
            int o = i & 63, in = i >> 6;
            g_woT[o * 64 + in] = __float2bfloat16(Wo[in * 64 + o]);
        }
    }
}

// ---------------- kernel 2: split-K flash attention (partials) --------------
// Grid 128 = b(4) x qt(16) x half(2). CTA: 256 threads = 8 warps, 256 queries
// (32/warp, two 16-row subtiles sharing every B fragment), 2048 keys.
// Fixed-max log2 softmax; writes unnormalized partial O + l.
#define SSTR 72                    // smem row stride in bf16 (144B)
#define KVB  (64 * SSTR * 2)       // bytes per tile stage

__global__ void __launch_bounds__(256, 1) attn_kernel()
{
    extern __shared__ __align__(16) __nv_bfloat16 dsm[];
    __nv_bfloat16* Qs  = dsm;                   // 256 x SSTR
    __nv_bfloat16* Ks  = Qs + 256 * SSTR;       // 3 stages x 64 x SSTR
    __nv_bfloat16* Vts = Ks + 3 * 64 * SSTR;    // 3 stages x 64 x SSTR

    int bx = blockIdx.x;
    int b = bx >> 5, rem = bx & 31;
    int qt = rem >> 1, half = rem & 1;
    int t0 = qt * 256, kt0 = half * 32;
    int tid = threadIdx.x, warp = tid >> 5, lane = tid & 31;
    int qr = warp * 32;
    int g = lane >> 2, c4 = lane & 3;

    const __nv_bfloat16* qg  = g_qb  + ((size_t)b * 4096 + t0) * 64;
    const __nv_bfloat16* kgb = g_kb  + ((size_t)b * 4096 + kt0 * 64) * 64;
    const __nv_bfloat16* vtg = g_vtb + (size_t)b * 64 * 4096 + kt0 * 64;

    unsigned qbase = (unsigned)__cvta_generic_to_shared(Qs);
    unsigned kbase = (unsigned)__cvta_generic_to_shared(Ks);
    unsigned vbase = (unsigned)__cvta_generic_to_shared(Vts);

    int lrow0 = tid >> 3, lrow1 = lrow0 + 32, lcc = tid & 7;
    unsigned o0 = (unsigned)((lrow0 * SSTR + lcc * 8) * 2);
    unsigned o1 = (unsigned)((lrow1 * SSTR + lcc * 8) * 2);
    const __nv_bfloat16* ksrc0 = kgb + lrow0 * 64 + lcc * 8;
    const __nv_bfloat16* ksrc1 = kgb + lrow1 * 64 + lcc * 8;
    const __nv_bfloat16* vsrc0 = vtg + (size_t)lrow0 * 4096 + lcc * 8;
    const __nv_bfloat16* vsrc1 = vtg + (size_t)lrow1 * 4096 + lcc * 8;

    // ---- prologue: Q (8 chunks/thread) + tile0 (G0), tile1 (G1) ----
    #pragma unroll
    for (int j = 0; j < 8; j++) {
        int i = tid + j * 256, row = i >> 3, cc = i & 7;
        CP_ASYNC16(qbase + (unsigned)((row * SSTR + cc * 8) * 2),
                   qg + row * 64 + cc * 8);
    }
    CP_ASYNC16(kbase + o0, ksrc0);
    CP_ASYNC16(kbase + o1, ksrc1);
    CP_ASYNC16(vbase + o0, vsrc0);
    CP_ASYNC16(vbase + o1, vsrc1);
    CP_COMMIT();   // G0
    CP_ASYNC16(kbase + KVB + o0, ksrc0 + 64 * 64);
    CP_ASYNC16(kbase + KVB + o1, ksrc1 + 64 * 64);
    CP_ASYNC16(vbase + KVB + o0, vsrc0 + 64);
    CP_ASYNC16(vbase + KVB + o1, vsrc1 + 64);
    CP_COMMIT();   // G1

    CP_WAIT1();    // Q + tile0 resident
    __syncthreads();

    int arow = (lane & 7) + (lane & 8);
    int acol = (lane >> 4) << 3;
    unsigned aaddr0 = qbase + (unsigned)(((qr + arow) * SSTR + acol) * 2);
    unsigned aaddr1 = qbase + (unsigned)(((qr + 16 + arow) * SSTR + acol) * 2);
    unsigned aQ0[4][4], aQ1[4][4];
    #pragma unroll
    for (int kk = 0; kk < 4; kk++) {
        LDSM4(aQ0[kk][0], aQ0[kk][1], aQ0[kk][2], aQ0[kk][3], aaddr0 + kk * 32);
        LDSM4(aQ1[kk][0], aQ1[kk][1], aQ1[kk][2], aQ1[kk][3], aaddr1 + kk * 32);
    }

    unsigned boff = (unsigned)((((lane & 7) + ((lane & 16) >> 1)) * SSTR + (lane & 8)) * 2);

    float of0[8][4], of1[8][4];
    #pragma unroll
    for (int nn = 0; nn < 8; nn++)
        #pragma unroll
        for (int i = 0; i < 4; i++) { of0[nn][i] = 0.f; of1[nn][i] = 0.f; }
    float l00 = 0.f, l01 = 0.f, l10 = 0.f, l11 = 0.f;

    int stc = 0;
    for (int t = 0; t < 32; t++) {
        CP_WAIT1();
        __syncthreads();

        if (t + 2 < 32) {
            unsigned st = (unsigned)((t + 2) % 3) * KVB;
            const __nv_bfloat16* k0 = ksrc0 + (size_t)(t + 2) * 64 * 64;
            const __nv_bfloat16* k1 = ksrc1 + (size_t)(t + 2) * 64 * 64;
            CP_ASYNC16(kbase + st + o0, k0);
            CP_ASYNC16(kbase + st + o1, k1);
            CP_ASYNC16(vbase + st + o0, vsrc0 + (t + 2) * 64);
            CP_ASYNC16(vbase + st + o1, vsrc1 + (t + 2) * 64);
        }
        CP_COMMIT();

        unsigned kb = kbase + (unsigned)(stc * KVB) + boff;
        unsigned vb = vbase + (unsigned)(stc * KVB) + boff;
        stc = (stc == 2) ? 0 : stc + 1;

        // ---- S = Q K^T for both 16-row subtiles (B frags shared) ----
        float s0[8][4], s1[8][4];
        #pragma unroll
        for (int nn = 0; nn < 8; nn++)
            #pragma unroll
            for (int i = 0; i < 4; i++) { s0[nn][i] = 0.f; s1[nn][i] = 0.f; }
        #pragma unroll
        for (int kk = 0; kk < 4; kk++) {
            #pragma unroll
            for (int np = 0; np < 4; np++) {
                unsigned b0, b1, b2, b3;
                LDSM4(b0, b1, b2, b3, kb + (unsigned)((np * 16 * SSTR + kk * 16) * 2));
                MMA16816(s0[2 * np],     aQ0[kk][0], aQ0[kk][1], aQ0[kk][2], aQ0[kk][3], b0, b1);
                MMA16816(s0[2 * np + 1], aQ0[kk][0], aQ0[kk][1], aQ0[kk][2], aQ0[kk][3], b2, b3);
                MMA16816(s1[2 * np],     aQ1[kk][0], aQ1[kk][1], aQ1[kk][2], aQ1[kk][3], b0, b1);
                MMA16816(s1[2 * np + 1], aQ1[kk][0], aQ1[kk][1], aQ1[kk][2], aQ1[kk][3], b2, b3);
            }
        }

        // ---- fixed-max softmax: p = 2^s ----
        #pragma unroll
        for (int nn = 0; nn < 8; nn++) {
            s0[nn][0] = ex2(s0[nn][0]); s0[nn][1] = ex2(s0[nn][1]);
            s0[nn][2] = ex2(s0[nn][2]); s0[nn][3] = ex2(s0[nn][3]);
            l00 += s0[nn][0] + s0[nn][1];
            l01 += s0[nn][2] + s0[nn][3];
            s1[nn][0] = ex2(s1[nn][0]); s1[nn][1] = ex2(s1[nn][1]);
            s1[nn][2] = ex2(s1[nn][2]); s1[nn][3] = ex2(s1[nn][3]);
            l10 += s1[nn][0] + s1[nn][1];
            l11 += s1[nn][2] + s1[nn][3];
        }

        // ---- O += P V (B frags shared across subtiles) ----
        #pragma unroll
        for (int kk = 0; kk < 4; kk++) {
            unsigned a00 = pk2(s0[2 * kk][1],     s0[2 * kk][0]);
            unsigned a01 = pk2(s0[2 * kk][3],     s0[2 * kk][2]);
            unsigned a02 = pk2(s0[2 * kk + 1][1], s0[2 * kk + 1][0]);
            unsigned a03 = pk2(s0[2 * kk + 1][3], s0[2 * kk + 1][2]);
            unsigned a10 = pk2(s1[2 * kk][1],     s1[2 * kk][0]);
            unsigned a11 = pk2(s1[2 * kk][3],     s1[2 * kk][2]);
            unsigned a12 = pk2(s1[2 * kk + 1][1], s1[2 * kk + 1][0]);
            unsigned a13 = pk2(s1[2 * kk + 1][3], s1[2 * kk + 1][2]);
            #pragma unroll
            for (int np = 0; np < 4; np++) {
                unsigned b0, b1, b2, b3;
                LDSM4(b0, b1, b2, b3, vb + (unsigned)((np * 16 * SSTR + kk * 16) * 2));
                MMA16816(of0[2 * np],     a00, a01, a02, a03, b0, b1);
                MMA16816(of0[2 * np + 1], a00, a01, a02, a03, b2, b3);
                MMA16816(of1[2 * np],     a10, a11, a12, a13, b0, b1);
                MMA16816(of1[2 * np + 1], a10, a11, a12, a13, b2, b3);
            }
        }
    }

    // ---- quad-reduce row sums, store partials ----
    #pragma unroll
    for (int off = 1; off <= 2; off <<= 1) {
        l00 += __shfl_xor_sync(0xffffffffu, l00, off);
        l01 += __shfl_xor_sync(0xffffffffu, l01, off);
        l10 += __shfl_xor_sync(0xffffffffu, l10, off);
        l11 += __shfl_xor_sync(0xffffffffu, l11, off);
    }
    int r0g = qr + g, r1g = qr + 8 + g, r2g = qr + 16 + g, r3g = qr + 24 + g;
    if (c4 == 0) {
        float* lp = g_pl + (size_t)half * NTOK + (size_t)b * 4096 + t0;
        lp[r0g] = l00; lp[r1g] = l01; lp[r2g] = l10; lp[r3g] = l11;
    }
    float* po = g_po + (size_t)half * NTOK * 64 + ((size_t)b * 4096 + t0) * 64;
    #pragma unroll
    for (int nn = 0; nn < 8; nn++) {
        int col = nn * 8 + c4 * 2;
        *(float2*)(po + (size_t)r0g * 64 + col) = make_float2(of0[nn][0], of0[nn][1]);
        *(float2*)(po + (size_t)r1g * 64 + col) = make_float2(of0[nn][2], of0[nn][3]);
        *(float2*)(po + (size_t)r2g * 64 + col) = make_float2(of1[nn][0], of1[nn][1]);
        *(float2*)(po + (size_t)r3g * 64 + col) = make_float2(of1[nn][2], of1[nn][3]);
    }
}

// ---------------- kernel 3: combine + Wo + residual -------------------------
// Grid 128 = b(4) x 32 tiles of 128 tokens. 256 threads = 8 warps x 16 rows.
__global__ void __launch_bounds__(256) combine_kernel(
    const float* __restrict__ bo, float* __restrict__ out)
{
    __shared__ __align__(16) __nv_bfloat16 Obf[128 * SSTR];
    __shared__ __align__(16) __nv_bfloat16 Wt[64 * SSTR];

    int bx = blockIdx.x;
    int b = bx >> 5, qt = bx & 31;
    int t0 = qt * 128;
    int tid = threadIdx.x, warp = tid >> 5, lane = tid & 31;
    int qr = warp * 16;
    int g = lane >> 2, c4 = lane & 3;

    // normalize O = (O0+O1)/(l0+l1) -> bf16 smem
    {
        int row = tid >> 1, colh = (tid & 1) * 32;
        size_t tok = (size_t)b * 4096 + t0 + row;
        float inv = 1.f / (g_pl[tok] + g_pl[NTOK + tok]);
        const float4* p0 = (const float4*)(g_po + tok * 64 + colh);
        const float4* p1 = (const float4*)(g_po + (size_t)NTOK * 64 + tok * 64 + colh);
        unsigned* dst = (unsigned*)(Obf + row * SSTR + colh);
        #pragma unroll
        for (int j = 0; j < 8; j++) {
            float4 a = p0[j], c = p1[j];
            float x0 = (a.x + c.x) * inv, y0 = (a.y + c.y) * inv;
            float z0 = (a.z + c.z) * inv, w0 = (a.w + c.w) * inv;
            dst[j * 2 + 0] = pk2(y0, x0);
            dst[j * 2 + 1] = pk2(w0, z0);
        }
    }
    for (int i = tid; i < 512; i += 256) {
        int row = i >> 3, cc = i & 7;
        *(float4*)(Wt + row * SSTR + cc * 8) =
            *(const float4*)(g_woT + row * 64 + cc * 8);
    }
    __syncthreads();

    unsigned obase = (unsigned)__cvta_generic_to_shared(Obf);
    unsigned wbase = (unsigned)__cvta_generic_to_shared(Wt);
    int arow = (lane & 7) + (lane & 8);
    int acol = (lane >> 4) << 3;
    unsigned aaddr = obase + (unsigned)(((qr + arow) * SSTR + acol) * 2);
    unsigned boff = (unsigned)((((lane & 7) + ((lane & 16) >> 1)) * SSTR + (lane & 8)) * 2);

    float r[8][4];
    #pragma unroll
    for (int nn = 0; nn < 8; nn++)
        #pragma unroll
        for (int i = 0; i < 4; i++) r[nn][i] = 0.f;
    #pragma unroll
    for (int kk = 0; kk < 4; kk++) {
        unsigned a0, a1, a2, a3;
        LDSM4(a0, a1, a2, a3, aaddr + kk * 32);
        #pragma unroll
        for (int np = 0; np < 4; np++) {
            unsigned b0, b1, b2, b3;
            LDSM4(b0, b1, b2, b3, wbase + boff + (unsigned)((np * 16 * SSTR + kk * 16) * 2));
            MMA16816(r[2 * np],     a0, a1, a2, a3, b0, b1);
            MMA16816(r[2 * np + 1], a0, a1, a2, a3, b2, b3);
        }
    }

    #pragma unroll
    for (int nn = 0; nn < 8; nn++) {
        int col = nn * 8 + c4 * 2;
        float2 bv = *(const float2*)(bo + col);
        size_t i0 = ((size_t)b * 4096 + t0 + qr + g) * 64 + col;
        float2 x0 = *(const float2*)(g_xn + i0);
        *(float2*)(out + i0) = make_float2(r[nn][0] + bv.x + x0.x,
                                           r[nn][1] + bv.y + x0.y);
        size_t i1 = i0 + (size_t)8 * 64;
        float2 x1 = *(const float2*)(g_xn + i1);
        *(float2*)(out + i1) = make_float2(r[nn][2] + bv.x + x1.x,
                                           r[nn][3] + bv.y + x1.y);
    }
}

// ---------------- launch ----------------------------------------------------
extern "C" void kernel_launch(void* const* d_in, const int* in_sizes, int n_in,
                              void* d_out, int out_size)
{
    const float* x     = (const float*)d_in[0];
    const float* gamma = (const float*)d_in[1];
    const float* beta  = (const float*)d_in[2];
    const float* Wq    = (const float*)d_in[3];
    const float* bq    = (const float*)d_in[4];
    const float* Wk    = (const float*)d_in[5];
    const float* bk    = (const float*)d_in[6];
    const float* Wv    = (const float*)d_in[7];
    const float* bv    = (const float*)d_in[8];
    const float* Wo    = (const float*)d_in[9];
    const float* bo    = (const float*)d_in[10];
    float* out = (float*)d_out;

    const int attn_smem = (256 * SSTR + 6 * 64 * SSTR) * 2;   // 92160 B
    cudaFuncSetAttribute(attn_kernel,
                         cudaFuncAttributeMaxDynamicSharedMemorySize, attn_smem);

    gn_qkv_kernel<<<BATCH * 64, 256>>>(x, gamma, beta, Wq, bq, Wk, bk, Wv, bv, Wo);
    attn_kernel<<<128, 256, attn_smem>>>();
    combine_kernel<<<128, 256>>>(bo, out);
}

// round 11
// speedup vs baseline: 1.1710x; 1.1710x over previous
#include <cuda_runtime.h>
#include <cuda_bf16.h>
#include <cstdint>

// Problem constants: B=4, H=64, W=64, C=64, GROUPS=8
#define BATCH 4
#define GROUPS 8
#define SEQ 4096
#define NTOK (BATCH * SEQ)
#define GN_EPS 1e-5f
#define SCALE 0.125f
#define LOG2E 1.4426950408889634f

// ---------------- scratch ---------------------------------------------------
__device__ float g_xn[NTOK * 64];                        // fp32 [b][t][c]
__device__ __nv_bfloat16 g_qb[NTOK * 64];                // bf16 [b][t][d] (pre-scaled)
__device__ __nv_bfloat16 g_kb[NTOK * 64];                // bf16 [b][t][d]
__device__ __nv_bfloat16 g_vtb[BATCH * 64 * SEQ];        // bf16 [b][d][t]
__device__ __nv_bfloat16 g_woT[64 * 64];                 // bf16 [out][in]
__device__ float g_po[2 * NTOK * 64];                    // partial O (unnormalized)
__device__ float g_pl[2 * NTOK];                         // partial row sums

// ---------------- PTX helpers ----------------------------------------------
#define LDSM4(r0, r1, r2, r3, addr)                                          \
    asm volatile("ldmatrix.sync.aligned.m8n8.x4.shared.b16 {%0,%1,%2,%3}, [%4];" \
                 : "=r"(r0), "=r"(r1), "=r"(r2), "=r"(r3) : "r"(addr))

#define MMA16816(d, a0, a1, a2, a3, b0, b1)                                  \
    asm volatile("mma.sync.aligned.m16n8k16.row.col.f32.bf16.bf16.f32 "      \
                 "{%0,%1,%2,%3}, {%4,%5,%6,%7}, {%8,%9}, {%0,%1,%2,%3};"     \
                 : "+f"(d[0]), "+f"(d[1]), "+f"(d[2]), "+f"(d[3])            \
                 : "r"(a0), "r"(a1), "r"(a2), "r"(a3), "r"(b0), "r"(b1))

#define CP_ASYNC16(dst, src)                                                 \
    asm volatile("cp.async.cg.shared.global [%0], [%1], 16;"                 \
                 :: "r"(dst), "l"(src))
#define CP_COMMIT()  asm volatile("cp.async.commit_group;")
#define CP_WAIT1()   asm volatile("cp.async.wait_group 1;")

__device__ __forceinline__ unsigned pk2(float hi, float lo) {
    unsigned d;
    asm("cvt.rn.bf16x2.f32 %0, %1, %2;" : "=r"(d) : "f"(hi), "f"(lo));
    return d;
}
__device__ __forceinline__ float ex2(float x) {
    float r;
    asm("ex2.approx.f32 %0, %1;" : "=f"(r) : "f"(x));
    return r;
}

// ---------------- kernel 1: fused GN stats + xn + Q/K/V via mma (+WoT) ------
// Grid 128 = b(4) x tile(32). CTA: 256 threads = 8 warps, 128 tokens
// (= h rows 2*tile, 2*tile+1; one group). A-frags of xn shared across the
// three projection GEMMs; SCALE*log2e folded into Wq/bq.
__global__ void __launch_bounds__(256) gn_qkv_kernel(
    const float* __restrict__ x,
    const float* __restrict__ gamma, const float* __restrict__ beta,
    const float* __restrict__ Wq, const float* __restrict__ bq,
    const float* __restrict__ Wk, const float* __restrict__ bk,
    const float* __restrict__ Wv, const float* __restrict__ bv,
    const float* __restrict__ Wo)
{
    __shared__ __align__(16) __nv_bfloat16 xs16[128 * 72];   // xn bf16 [tok][j]
    __shared__ __align__(16) __nv_bfloat16 wt[64 * 72];      // W^T bf16 [c][j]
    __shared__ __align__(16) __nv_bfloat16 vsm[64 * 136];    // V^T bf16 [d][tok]

    int blk = blockIdx.x;             // b*32 + tile
    int b = blk >> 5, tile = blk & 31;
    int h0 = tile * 2, gg = h0 >> 3;
    int tid = threadIdx.x, warp = tid >> 5, lane = tid & 31;

    // ---- group statistics (group gg of batch b: 32768 floats) --------------
    const float4* gp = (const float4*)(x + (size_t)(b * 64 + gg * 8) * 4096);
    float s = 0.f, s2 = 0.f;
    #pragma unroll 8
    for (int i = tid; i < 8192; i += 256) {
        float4 v = gp[i];
        s  += v.x + v.y + v.z + v.w;
        s2 += v.x * v.x + v.y * v.y + v.z * v.z + v.w * v.w;
    }
    float* sh1 = (float*)vsm;
    float* sh2 = sh1 + 256;
    sh1[tid] = s; sh2[tid] = s2;
    __syncthreads();
    for (int st = 128; st > 0; st >>= 1) {
        if (tid < st) { sh1[tid] += sh1[tid + st]; sh2[tid] += sh2[tid + st]; }
        __syncthreads();
    }
    if (tid == 0) {
        float mean = sh1[0] * (1.f / 32768.f);
        float var  = sh2[0] * (1.f / 32768.f) - mean * mean;
        sh1[0] = mean;
        sh1[1] = rsqrtf(var + GN_EPS);
    }
    __syncthreads();
    float mean = sh1[0], rstd = sh1[1];
    __syncthreads();

    float a0 = rstd * gamma[h0],     c00 = beta[h0]     - mean * a0;
    float a1 = rstd * gamma[h0 + 1], c01 = beta[h0 + 1] - mean * a1;

    // ---- xn: 128 tokens x 64c -> g_xn fp32 + xs16 bf16 ---------------------
    const float4* xp  = (const float4*)(x    + (size_t)(b * 64 + h0) * 4096);
    float4*       xng = (float4*)(g_xn + (size_t)(b * 64 + h0) * 4096);
    #pragma unroll
    for (int r = 0; r < 8; r++) {
        int i4 = tid + r * 256;
        float4 v = xp[i4];
        int e = i4 * 4, row = e >> 6, c = e & 63;
        float aa = (row & 64) ? a1 : a0;
        float cc = (row & 64) ? c01 : c00;
        v.x = v.x * aa + cc; v.y = v.y * aa + cc;
        v.z = v.z * aa + cc; v.w = v.w * aa + cc;
        xng[i4] = v;
        *(uint2*)(xs16 + row * 72 + c) = make_uint2(pk2(v.y, v.x), pk2(v.w, v.z));
    }
    __syncthreads();

    // ---- A fragments (xn) : loaded once, reused for Q/K/V ------------------
    int qr = warp * 16;
    int arow = (lane & 7) + (lane & 8);
    int acol = (lane >> 4) << 3;
    unsigned xbase = (unsigned)__cvta_generic_to_shared(xs16);
    unsigned wbase = (unsigned)__cvta_generic_to_shared(wt);
    unsigned aaddr = xbase + (unsigned)(((qr + arow) * 72 + acol) * 2);
    unsigned aX[4][4];
    #pragma unroll
    for (int kk = 0; kk < 4; kk++)
        LDSM4(aX[kk][0], aX[kk][1], aX[kk][2], aX[kk][3], aaddr + kk * 32);

    unsigned boff = (unsigned)((((lane & 7) + ((lane & 16) >> 1)) * 72 + (lane & 8)) * 2);
    int g = lane >> 2, c4 = lane & 3;
    const float SC2 = SCALE * LOG2E;

    #pragma unroll
    for (int mtx = 0; mtx < 3; mtx++) {
        const float* Wm = (mtx == 0) ? Wq : (mtx == 1) ? Wk : Wv;
        const float* bm = (mtx == 0) ? bq : (mtx == 1) ? bk : bv;
        float qs = (mtx == 0) ? SC2 : 1.f;

        __syncthreads();   // previous mma reads of wt done
        for (int i = tid; i < 4096; i += 256) {
            int j = i >> 6, c = i & 63;
            wt[c * 72 + j] = __float2bfloat16(Wm[i] * qs);
        }
        __syncthreads();

        float sacc[8][4];
        #pragma unroll
        for (int nn = 0; nn < 8; nn++)
            #pragma unroll
            for (int i = 0; i < 4; i++) sacc[nn][i] = 0.f;
        #pragma unroll
        for (int kk = 0; kk < 4; kk++) {
            #pragma unroll
            for (int np = 0; np < 4; np++) {
                unsigned b0, b1, b2, b3;
                LDSM4(b0, b1, b2, b3, wbase + boff + (unsigned)((np * 16 * 72 + kk * 16) * 2));
                MMA16816(sacc[2 * np],     aX[kk][0], aX[kk][1], aX[kk][2], aX[kk][3], b0, b1);
                MMA16816(sacc[2 * np + 1], aX[kk][0], aX[kk][1], aX[kk][2], aX[kk][3], b2, b3);
            }
        }

        if (mtx < 2) {
            __nv_bfloat16* og = mtx ? g_kb : g_qb;
            size_t tbase = ((size_t)b * 4096 + tile * 128 + qr + g) * 64;
            #pragma unroll
            for (int nn = 0; nn < 8; nn++) {
                int col = nn * 8 + c4 * 2;
                float b0v = bm[col] * qs, b1v = bm[col + 1] * qs;
                *(unsigned*)(og + tbase + col) =
                    pk2(sacc[nn][1] + b1v, sacc[nn][0] + b0v);
                *(unsigned*)(og + tbase + (size_t)8 * 64 + col) =
                    pk2(sacc[nn][3] + b1v, sacc[nn][2] + b0v);
            }
        } else {
            int tok0 = qr + g, tok1 = qr + 8 + g;
            #pragma unroll
            for (int nn = 0; nn < 8; nn++) {
                int col = nn * 8 + c4 * 2;
                float b0v = bm[col], b1v = bm[col + 1];
                vsm[col * 136 + tok0]       = __float2bfloat16(sacc[nn][0] + b0v);
                vsm[(col + 1) * 136 + tok0] = __float2bfloat16(sacc[nn][1] + b1v);
                vsm[col * 136 + tok1]       = __float2bfloat16(sacc[nn][2] + b0v);
                vsm[(col + 1) * 136 + tok1] = __float2bfloat16(sacc[nn][3] + b1v);
            }
        }
    }
    __syncthreads();

    // ---- V copy-out: vsm [d][tok] -> g_vtb [b][d][t0+tok] vectorized -------
    {
        int d = tid >> 2, seg = tid & 3;
        const float4* src = (const float4*)(vsm + d * 136 + seg * 32);
        float4* dst = (float4*)(g_vtb + ((size_t)b * 64 + d) * 4096 + tile * 128 + seg * 32);
        dst[0] = src[0]; dst[1] = src[1]; dst[2] = src[2]; dst[3] = src[3];
    }

    if (blk == 0) {
        for (int i = tid; i < 4096; i += 256) {
            int o = i & 63, in = i >> 6;
            g_woT[o * 64 + in] = __float2bfloat16(Wo[in * 64 + o]);
        }
    }
}

// ---------------- kernel 2: split-K flash attention (partials) --------------
// Grid 128 = b(4) x qt(16) x half(2). CTA: 256 threads = 8 warps, 256 queries
// (32/warp, two 16-row subtiles sharing every B fragment), 2048 keys.
#define SSTR 72                    // smem row stride in bf16 (144B)
#define KVB  (64 * SSTR * 2)       // bytes per tile stage

__global__ void __launch_bounds__(256, 1) attn_kernel()
{
    extern __shared__ __align__(16) __nv_bfloat16 dsm[];
    __nv_bfloat16* Qs  = dsm;                   // 256 x SSTR
    __nv_bfloat16* Ks  = Qs + 256 * SSTR;       // 3 stages x 64 x SSTR
    __nv_bfloat16* Vts = Ks + 3 * 64 * SSTR;    // 3 stages x 64 x SSTR

    int bx = blockIdx.x;
    int b = bx >> 5, rem = bx & 31;
    int qt = rem >> 1, half = rem & 1;
    int t0 = qt * 256, kt0 = half * 32;
    int tid = threadIdx.x, warp = tid >> 5, lane = tid & 31;
    int qr = warp * 32;
    int g = lane >> 2, c4 = lane & 3;

    const __nv_bfloat16* qg  = g_qb  + ((size_t)b * 4096 + t0) * 64;
    const __nv_bfloat16* kgb = g_kb  + ((size_t)b * 4096 + kt0 * 64) * 64;
    const __nv_bfloat16* vtg = g_vtb + (size_t)b * 64 * 4096 + kt0 * 64;

    unsigned qbase = (unsigned)__cvta_generic_to_shared(Qs);
    unsigned kbase = (unsigned)__cvta_generic_to_shared(Ks);
    unsigned vbase = (unsigned)__cvta_generic_to_shared(Vts);

    int lrow0 = tid >> 3, lrow1 = lrow0 + 32, lcc = tid & 7;
    unsigned o0 = (unsigned)((lrow0 * SSTR + lcc * 8) * 2);
    unsigned o1 = (unsigned)((lrow1 * SSTR + lcc * 8) * 2);
    const __nv_bfloat16* ksrc0 = kgb + lrow0 * 64 + lcc * 8;
    const __nv_bfloat16* ksrc1 = kgb + lrow1 * 64 + lcc * 8;
    const __nv_bfloat16* vsrc0 = vtg + (size_t)lrow0 * 4096 + lcc * 8;
    const __nv_bfloat16* vsrc1 = vtg + (size_t)lrow1 * 4096 + lcc * 8;

    #pragma unroll
    for (int j = 0; j < 8; j++) {
        int i = tid + j * 256, row = i >> 3, cc = i & 7;
        CP_ASYNC16(qbase + (unsigned)((row * SSTR + cc * 8) * 2),
                   qg + row * 64 + cc * 8);
    }
    CP_ASYNC16(kbase + o0, ksrc0);
    CP_ASYNC16(kbase + o1, ksrc1);
    CP_ASYNC16(vbase + o0, vsrc0);
    CP_ASYNC16(vbase + o1, vsrc1);
    CP_COMMIT();   // G0
    CP_ASYNC16(kbase + KVB + o0, ksrc0 + 64 * 64);
    CP_ASYNC16(kbase + KVB + o1, ksrc1 + 64 * 64);
    CP_ASYNC16(vbase + KVB + o0, vsrc0 + 64);
    CP_ASYNC16(vbase + KVB + o1, vsrc1 + 64);
    CP_COMMIT();   // G1

    CP_WAIT1();
    __syncthreads();

    int arow = (lane & 7) + (lane & 8);
    int acol = (lane >> 4) << 3;
    unsigned aaddr0 = qbase + (unsigned)(((qr + arow) * SSTR + acol) * 2);
    unsigned aaddr1 = qbase + (unsigned)(((qr + 16 + arow) * SSTR + acol) * 2);
    unsigned aQ0[4][4], aQ1[4][4];
    #pragma unroll
    for (int kk = 0; kk < 4; kk++) {
        LDSM4(aQ0[kk][0], aQ0[kk][1], aQ0[kk][2], aQ0[kk][3], aaddr0 + kk * 32);
        LDSM4(aQ1[kk][0], aQ1[kk][1], aQ1[kk][2], aQ1[kk][3], aaddr1 + kk * 32);
    }

    unsigned boff = (unsigned)((((lane & 7) + ((lane & 16) >> 1)) * SSTR + (lane & 8)) * 2);

    float of0[8][4], of1[8][4];
    #pragma unroll
    for (int nn = 0; nn < 8; nn++)
        #pragma unroll
        for (int i = 0; i < 4; i++) { of0[nn][i] = 0.f; of1[nn][i] = 0.f; }
    float l00 = 0.f, l01 = 0.f, l10 = 0.f, l11 = 0.f;

    int stc = 0;
    for (int t = 0; t < 32; t++) {
        CP_WAIT1();
        __syncthreads();

        if (t + 2 < 32) {
            unsigned st = (unsigned)((t + 2) % 3) * KVB;
            const __nv_bfloat16* k0 = ksrc0 + (size_t)(t + 2) * 64 * 64;
            const __nv_bfloat16* k1 = ksrc1 + (size_t)(t + 2) * 64 * 64;
            CP_ASYNC16(kbase + st + o0, k0);
            CP_ASYNC16(kbase + st + o1, k1);
            CP_ASYNC16(vbase + st + o0, vsrc0 + (t + 2) * 64);
            CP_ASYNC16(vbase + st + o1, vsrc1 + (t + 2) * 64);
        }
        CP_COMMIT();

        unsigned kb = kbase + (unsigned)(stc * KVB) + boff;
        unsigned vb = vbase + (unsigned)(stc * KVB) + boff;
        stc = (stc == 2) ? 0 : stc + 1;

        float s0[8][4], s1[8][4];
        #pragma unroll
        for (int nn = 0; nn < 8; nn++)
            #pragma unroll
            for (int i = 0; i < 4; i++) { s0[nn][i] = 0.f; s1[nn][i] = 0.f; }
        #pragma unroll
        for (int kk = 0; kk < 4; kk++) {
            #pragma unroll
            for (int np = 0; np < 4; np++) {
                unsigned b0, b1, b2, b3;
                LDSM4(b0, b1, b2, b3, kb + (unsigned)((np * 16 * SSTR + kk * 16) * 2));
                MMA16816(s0[2 * np],     aQ0[kk][0], aQ0[kk][1], aQ0[kk][2], aQ0[kk][3], b0, b1);
                MMA16816(s0[2 * np + 1], aQ0[kk][0], aQ0[kk][1], aQ0[kk][2], aQ0[kk][3], b2, b3);
                MMA16816(s1[2 * np],     aQ1[kk][0], aQ1[kk][1], aQ1[kk][2], aQ1[kk][3], b0, b1);
                MMA16816(s1[2 * np + 1], aQ1[kk][0], aQ1[kk][1], aQ1[kk][2], aQ1[kk][3], b2, b3);
            }
        }

        #pragma unroll
        for (int nn = 0; nn < 8; nn++) {
            s0[nn][0] = ex2(s0[nn][0]); s0[nn][1] = ex2(s0[nn][1]);
            s0[nn][2] = ex2(s0[nn][2]); s0[nn][3] = ex2(s0[nn][3]);
            l00 += s0[nn][0] + s0[nn][1];
            l01 += s0[nn][2] + s0[nn][3];
            s1[nn][0] = ex2(s1[nn][0]); s1[nn][1] = ex2(s1[nn][1]);
            s1[nn][2] = ex2(s1[nn][2]); s1[nn][3] = ex2(s1[nn][3]);
            l10 += s1[nn][0] + s1[nn][1];
            l11 += s1[nn][2] + s1[nn][3];
        }

        #pragma unroll
        for (int kk = 0; kk < 4; kk++) {
            unsigned a00 = pk2(s0[2 * kk][1],     s0[2 * kk][0]);
            unsigned a01 = pk2(s0[2 * kk][3],     s0[2 * kk][2]);
            unsigned a02 = pk2(s0[2 * kk + 1][1], s0[2 * kk + 1][0]);
            unsigned a03 = pk2(s0[2 * kk + 1][3], s0[2 * kk + 1][2]);
            unsigned a10 = pk2(s1[2 * kk][1],     s1[2 * kk][0]);
            unsigned a11 = pk2(s1[2 * kk][3],     s1[2 * kk][2]);
            unsigned a12 = pk2(s1[2 * kk + 1][1], s1[2 * kk + 1][0]);
            unsigned a13 = pk2(s1[2 * kk + 1][3], s1[2 * kk + 1][2]);
            #pragma unroll
            for (int np = 0; np < 4; np++) {
                unsigned b0, b1, b2, b3;
                LDSM4(b0, b1, b2, b3, vb + (unsigned)((np * 16 * SSTR + kk * 16) * 2));
                MMA16816(of0[2 * np],     a00, a01, a02, a03, b0, b1);
                MMA16816(of0[2 * np + 1], a00, a01, a02, a03, b2, b3);
                MMA16816(of1[2 * np],     a10, a11, a12, a13, b0, b1);
                MMA16816(of1[2 * np + 1], a10, a11, a12, a13, b2, b3);
            }
        }
    }

    #pragma unroll
    for (int off = 1; off <= 2; off <<= 1) {
        l00 += __shfl_xor_sync(0xffffffffu, l00, off);
        l01 += __shfl_xor_sync(0xffffffffu, l01, off);
        l10 += __shfl_xor_sync(0xffffffffu, l10, off);
        l11 += __shfl_xor_sync(0xffffffffu, l11, off);
    }
    int r0g = qr + g, r1g = qr + 8 + g, r2g = qr + 16 + g, r3g = qr + 24 + g;
    if (c4 == 0) {
        float* lp = g_pl + (size_t)half * NTOK + (size_t)b * 4096 + t0;
        lp[r0g] = l00; lp[r1g] = l01; lp[r2g] = l10; lp[r3g] = l11;
    }
    float* po = g_po + (size_t)half * NTOK * 64 + ((size_t)b * 4096 + t0) * 64;
    #pragma unroll
    for (int nn = 0; nn < 8; nn++) {
        int col = nn * 8 + c4 * 2;
        *(float2*)(po + (size_t)r0g * 64 + col) = make_float2(of0[nn][0], of0[nn][1]);
        *(float2*)(po + (size_t)r1g * 64 + col) = make_float2(of0[nn][2], of0[nn][3]);
        *(float2*)(po + (size_t)r2g * 64 + col) = make_float2(of1[nn][0], of1[nn][1]);
        *(float2*)(po + (size_t)r3g * 64 + col) = make_float2(of1[nn][2], of1[nn][3]);
    }
}

// ---------------- kernel 3: combine + Wo + residual -------------------------
__global__ void __launch_bounds__(256) combine_kernel(
    const float* __restrict__ bo, float* __restrict__ out)
{
    __shared__ __align__(16) __nv_bfloat16 Obf[128 * SSTR];
    __shared__ __align__(16) __nv_bfloat16 Wt[64 * SSTR];

    int bx = blockIdx.x;
    int b = bx >> 5, qt = bx & 31;
    int t0 = qt * 128;
    int tid = threadIdx.x, warp = tid >> 5, lane = tid & 31;
    int qr = warp * 16;
    int g = lane >> 2, c4 = lane & 3;

    {
        int row = tid >> 1, colh = (tid & 1) * 32;
        size_t tok = (size_t)b * 4096 + t0 + row;
        float inv = 1.f / (g_pl[tok] + g_pl[NTOK + tok]);
        const float4* p0 = (const float4*)(g_po + tok * 64 + colh);
        const float4* p1 = (const float4*)(g_po + (size_t)NTOK * 64 + tok * 64 + colh);
        unsigned* dst = (unsigned*)(Obf + row * SSTR + colh);
        #pragma unroll
        for (int j = 0; j < 8; j++) {
            float4 a = p0[j], c = p1[j];
            float x0 = (a.x + c.x) * inv, y0 = (a.y + c.y) * inv;
            float z0 = (a.z + c.z) * inv, w0 = (a.w + c.w) * inv;
            dst[j * 2 + 0] = pk2(y0, x0);
            dst[j * 2 + 1] = pk2(w0, z0);
        }
    }
    for (int i = tid; i < 512; i += 256) {
        int row = i >> 3, cc = i & 7;
        *(float4*)(Wt + row * SSTR + cc * 8) =
            *(const float4*)(g_woT + row * 64 + cc * 8);
    }
    __syncthreads();

    unsigned obase = (unsigned)__cvta_generic_to_shared(Obf);
    unsigned wbase = (unsigned)__cvta_generic_to_shared(Wt);
    int arow = (lane & 7) + (lane & 8);
    int acol = (lane >> 4) << 3;
    unsigned aaddr = obase + (unsigned)(((qr + arow) * SSTR + acol) * 2);
    unsigned boff = (unsigned)((((lane & 7) + ((lane & 16) >> 1)) * SSTR + (lane & 8)) * 2);

    float r[8][4];
    #pragma unroll
    for (int nn = 0; nn < 8; nn++)
        #pragma unroll
        for (int i = 0; i < 4; i++) r[nn][i] = 0.f;
    #pragma unroll
    for (int kk = 0; kk < 4; kk++) {
        unsigned a0, a1, a2, a3;
        LDSM4(a0, a1, a2, a3, aaddr + kk * 32);
        #pragma unroll
        for (int np = 0; np < 4; np++) {
            unsigned b0, b1, b2, b3;
            LDSM4(b0, b1, b2, b3, wbase + boff + (unsigned)((np * 16 * SSTR + kk * 16) * 2));
            MMA16816(r[2 * np],     a0, a1, a2, a3, b0, b1);
            MMA16816(r[2 * np + 1], a0, a1, a2, a3, b2, b3);
        }
    }

    #pragma unroll
    for (int nn = 0; nn < 8; nn++) {
        int col = nn * 8 + c4 * 2;
        float2 bv = *(const float2*)(bo + col);
        size_t i0 = ((size_t)b * 4096 + t0 + qr + g) * 64 + col;
        float2 x0 = *(const float2*)(g_xn + i0);
        *(float2*)(out + i0) = make_float2(r[nn][0] + bv.x + x0.x,
                                           r[nn][1] + bv.y + x0.y);
        size_t i1 = i0 + (size_t)8 * 64;
        float2 x1 = *(const float2*)(g_xn + i1);
        *(float2*)(out + i1) = make_float2(r[nn][2] + bv.x + x1.x,
                                           r[nn][3] + bv.y + x1.y);
    }
}

// ---------------- launch ----------------------------------------------------
extern "C" void kernel_launch(void* const* d_in, const int* in_sizes, int n_in,
                              void* d_out, int out_size)
{
    const float* x     = (const float*)d_in[0];
    const float* gamma = (const float*)d_in[1];
    const float* beta  = (const float*)d_in[2];
    const float* Wq    = (const float*)d_in[3];
    const float* bq    = (const float*)d_in[4];
    const float* Wk    = (const float*)d_in[5];
    const float* bk    = (const float*)d_in[6];
    const float* Wv    = (const float*)d_in[7];
    const float* bv    = (const float*)d_in[8];
    const float* Wo    = (const float*)d_in[9];
    const float* bo    = (const float*)d_in[10];
    float* out = (float*)d_out;

    const int attn_smem = (256 * SSTR + 6 * 64 * SSTR) * 2;   // 92160 B
    cudaFuncSetAttribute(attn_kernel,
                         cudaFuncAttributeMaxDynamicSharedMemorySize, attn_smem);

    gn_qkv_kernel<<<BATCH * 32, 256>>>(x, gamma, beta, Wq, bq, Wk, bk, Wv, bv, Wo);
    attn_kernel<<<128, 256, attn_smem>>>();
    combine_kernel<<<128, 256>>>(bo, out);
}

// round 13
// speedup vs baseline: 1.2655x; 1.0807x over previous
#include <cuda_runtime.h>
#include <cuda_bf16.h>
#include <cstdint>

// Problem constants: B=4, H=64, W=64, C=64, GROUPS=8
#define BATCH 4
#define GROUPS 8
#define SEQ 4096
#define NTOK (BATCH * SEQ)
#define GN_EPS 1e-5f
#define SCALE 0.125f
#define LOG2E 1.4426950408889634f

// ---------------- scratch ---------------------------------------------------
__device__ float g_xn[NTOK * 64];                        // fp32 [b][t][c]
__device__ __nv_bfloat16 g_qb[NTOK * 64];                // bf16 [b][t][d] (pre-scaled)
__device__ __nv_bfloat16 g_kb[NTOK * 64];                // bf16 [b][t][d]
__device__ __nv_bfloat16 g_vtb[BATCH * 64 * SEQ];        // bf16 [b][d][t]
__device__ __nv_bfloat16 g_wqT[64 * 64];                 // Wq^T * SC2, bf16
__device__ __nv_bfloat16 g_wkT[64 * 64];                 // Wk^T bf16
__device__ __nv_bfloat16 g_wvT[64 * 64];                 // Wv^T bf16
__device__ __nv_bfloat16 g_woT[64 * 64];                 // Wo^T bf16
__device__ float g_po[2 * NTOK * 64];                    // partial O (unnormalized)
__device__ float g_pl[2 * NTOK];                         // partial row sums

// ---------------- PTX helpers ----------------------------------------------
#define LDSM4(r0, r1, r2, r3, addr)                                          \
    asm volatile("ldmatrix.sync.aligned.m8n8.x4.shared.b16 {%0,%1,%2,%3}, [%4];" \
                 : "=r"(r0), "=r"(r1), "=r"(r2), "=r"(r3) : "r"(addr))

#define MMA16816(d, a0, a1, a2, a3, b0, b1)                                  \
    asm volatile("mma.sync.aligned.m16n8k16.row.col.f32.bf16.bf16.f32 "      \
                 "{%0,%1,%2,%3}, {%4,%5,%6,%7}, {%8,%9}, {%0,%1,%2,%3};"     \
                 : "+f"(d[0]), "+f"(d[1]), "+f"(d[2]), "+f"(d[3])            \
                 : "r"(a0), "r"(a1), "r"(a2), "r"(a3), "r"(b0), "r"(b1))

#define CP_ASYNC16(dst, src)                                                 \
    asm volatile("cp.async.cg.shared.global [%0], [%1], 16;"                 \
                 :: "r"(dst), "l"(src))
#define CP_COMMIT()  asm volatile("cp.async.commit_group;")
#define CP_WAIT1()   asm volatile("cp.async.wait_group 1;")
#define CP_WAIT0()   asm volatile("cp.async.wait_group 0;")

__device__ __forceinline__ unsigned pk2(float hi, float lo) {
    unsigned d;
    asm("cvt.rn.bf16x2.f32 %0, %1, %2;" : "=r"(d) : "f"(hi), "f"(lo));
    return d;
}
__device__ __forceinline__ float ex2(float x) {
    float r;
    asm("ex2.approx.f32 %0, %1;" : "=f"(r) : "f"(x));
    return r;
}

// ---------------- kernel 0: weight transposes to bf16 -----------------------
// Grid 16 x 1024. CTA c: matrix m = c>>2, quarter q = c&3 (1024 elems each).
__global__ void wprep_kernel(const float* __restrict__ Wq,
                             const float* __restrict__ Wk,
                             const float* __restrict__ Wv,
                             const float* __restrict__ Wo)
{
    int m = blockIdx.x >> 2, q = blockIdx.x & 3;
    const float* src = (m == 0) ? Wq : (m == 1) ? Wk : (m == 2) ? Wv : Wo;
    __nv_bfloat16* dst = (m == 0) ? g_wqT : (m == 1) ? g_wkT
                       : (m == 2) ? g_wvT : g_woT;
    float sc = (m == 0) ? (SCALE * LOG2E) : 1.f;
    int i = q * 1024 + threadIdx.x;
    int o = i & 63, in = i >> 6;
    dst[o * 64 + in] = __float2bfloat16(src[i] * sc);
}

// ---------------- kernel 1: fused GN stats + xn + Q/K/V via mma -------------
// Grid 128 = b(4) x tile(32). CTA: 256 threads = 8 warps, 128 tokens.
// W^T tiles cp.async'd during stats; zero barriers between the 3 GEMMs.
#define QK_SMEM (128 * 72 * 2 + 3 * 64 * 72 * 2 + 64 * 136 * 2)   // 63488

__global__ void __launch_bounds__(256) gn_qkv_kernel(
    const float* __restrict__ x,
    const float* __restrict__ gamma, const float* __restrict__ beta,
    const float* __restrict__ bq, const float* __restrict__ bk,
    const float* __restrict__ bv)
{
    extern __shared__ __align__(16) char qsm[];
    __nv_bfloat16* xs16 = (__nv_bfloat16*)qsm;                 // [128][72]
    __nv_bfloat16* wt3  = (__nv_bfloat16*)(qsm + 18432);       // 3 x [64][72]
    __nv_bfloat16* vsm  = (__nv_bfloat16*)(qsm + 46080);       // [64][136]

    int blk = blockIdx.x;             // b*32 + tile
    int b = blk >> 5, tile = blk & 31;
    int h0 = tile * 2, gg = h0 >> 3;
    int tid = threadIdx.x, warp = tid >> 5, lane = tid & 31;

    unsigned xbase = (unsigned)__cvta_generic_to_shared(xs16);
    unsigned wbase = (unsigned)__cvta_generic_to_shared(wt3);

    // ---- issue W^T copies (overlap with the stats reads below) -------------
    {
        const __nv_bfloat16* wsrc[3] = { g_wqT, g_wkT, g_wvT };
        #pragma unroll
        for (int m = 0; m < 3; m++)
            for (int i = tid; i < 512; i += 256) {
                int row = i >> 3, cc = i & 7;
                CP_ASYNC16(wbase + (unsigned)((m * 64 * 72 + row * 72 + cc * 8) * 2),
                           wsrc[m] + row * 64 + cc * 8);
            }
        CP_COMMIT();
    }

    // ---- group statistics (group gg of batch b: 32768 floats) --------------
    const float4* gp = (const float4*)(x + (size_t)(b * 64 + gg * 8) * 4096);
    float s = 0.f, s2 = 0.f;
    #pragma unroll 8
    for (int i = tid; i < 8192; i += 256) {
        float4 v = gp[i];
        s  += v.x + v.y + v.z + v.w;
        s2 += v.x * v.x + v.y * v.y + v.z * v.z + v.w * v.w;
    }
    #pragma unroll
    for (int off = 16; off > 0; off >>= 1) {
        s  += __shfl_xor_sync(0xffffffffu, s, off);
        s2 += __shfl_xor_sync(0xffffffffu, s2, off);
    }
    float* red = (float*)vsm;
    if (lane == 0) { red[warp] = s; red[8 + warp] = s2; }
    __syncthreads();
    if (tid == 0) {
        float ts = 0.f, ts2 = 0.f;
        #pragma unroll
        for (int i = 0; i < 8; i++) { ts += red[i]; ts2 += red[8 + i]; }
        float mean = ts * (1.f / 32768.f);
        float var  = ts2 * (1.f / 32768.f) - mean * mean;
        red[16] = mean;
        red[17] = rsqrtf(var + GN_EPS);
    }
    __syncthreads();
    float mean = red[16], rstd = red[17];

    float a0 = rstd * gamma[h0],     c00 = beta[h0]     - mean * a0;
    float a1 = rstd * gamma[h0 + 1], c01 = beta[h0 + 1] - mean * a1;

    // ---- xn: 128 tokens x 64c -> g_xn fp32 + xs16 bf16 ---------------------
    const float4* xp  = (const float4*)(x    + (size_t)(b * 64 + h0) * 4096);
    float4*       xng = (float4*)(g_xn + (size_t)(b * 64 + h0) * 4096);
    #pragma unroll
    for (int r = 0; r < 8; r++) {
        int i4 = tid + r * 256;
        float4 v = xp[i4];
        int e = i4 * 4, row = e >> 6, c = e & 63;
        float aa = (row & 64) ? a1 : a0;
        float cc = (row & 64) ? c01 : c00;
        v.x = v.x * aa + cc; v.y = v.y * aa + cc;
        v.z = v.z * aa + cc; v.w = v.w * aa + cc;
        xng[i4] = v;
        *(uint2*)(xs16 + row * 72 + c) = make_uint2(pk2(v.y, v.x), pk2(v.w, v.z));
    }
    CP_WAIT0();        // W^T tiles resident
    __syncthreads();   // xs16 + wt3 visible to all

    // ---- A fragments (xn), reused for all three GEMMs ----------------------
    int qr = warp * 16;
    int arow = (lane & 7) + (lane & 8);
    int acol = (lane >> 4) << 3;
    unsigned aaddr = xbase + (unsigned)(((qr + arow) * 72 + acol) * 2);
    unsigned aX[4][4];
    #pragma unroll
    for (int kk = 0; kk < 4; kk++)
        LDSM4(aX[kk][0], aX[kk][1], aX[kk][2], aX[kk][3], aaddr + kk * 32);

    unsigned boff = (unsigned)((((lane & 7) + ((lane & 16) >> 1)) * 72 + (lane & 8)) * 2);
    int g = lane >> 2, c4 = lane & 3;
    const float SC2 = SCALE * LOG2E;

    #pragma unroll
    for (int mtx = 0; mtx < 3; mtx++) {
        const float* bm = (mtx == 0) ? bq : (mtx == 1) ? bk : bv;
        float qs = (mtx == 0) ? SC2 : 1.f;
        unsigned wb = wbase + (unsigned)(mtx * 64 * 72 * 2) + boff;

        float sacc[8][4];
        #pragma unroll
        for (int nn = 0; nn < 8; nn++)
            #pragma unroll
            for (int i = 0; i < 4; i++) sacc[nn][i] = 0.f;
        #pragma unroll
        for (int kk = 0; kk < 4; kk++) {
            #pragma unroll
            for (int np = 0; np < 4; np++) {
                unsigned b0, b1, b2, b3;
                LDSM4(b0, b1, b2, b3, wb + (unsigned)((np * 16 * 72 + kk * 16) * 2));
                MMA16816(sacc[2 * np],     aX[kk][0], aX[kk][1], aX[kk][2], aX[kk][3], b0, b1);
                MMA16816(sacc[2 * np + 1], aX[kk][0], aX[kk][1], aX[kk][2], aX[kk][3], b2, b3);
            }
        }

        if (mtx < 2) {
            __nv_bfloat16* og = mtx ? g_kb : g_qb;
            size_t tbase = ((size_t)b * 4096 + tile * 128 + qr + g) * 64;
            #pragma unroll
            for (int nn = 0; nn < 8; nn++) {
                int col = nn * 8 + c4 * 2;
                float b0v = bm[col] * qs, b1v = bm[col + 1] * qs;
                *(unsigned*)(og + tbase + col) =
                    pk2(sacc[nn][1] + b1v, sacc[nn][0] + b0v);
                *(unsigned*)(og + tbase + (size_t)8 * 64 + col) =
                    pk2(sacc[nn][3] + b1v, sacc[nn][2] + b0v);
            }
        } else {
            __syncthreads();   // red[] scratch reads long done; vsm reuse safe
            int tok0 = qr + g, tok1 = qr + 8 + g;
            #pragma unroll
            for (int nn = 0; nn < 8; nn++) {
                int col = nn * 8 + c4 * 2;
                float b0v = bm[col], b1v = bm[col + 1];
                vsm[col * 136 + tok0]       = __float2bfloat16(sacc[nn][0] + b0v);
                vsm[(col + 1) * 136 + tok0] = __float2bfloat16(sacc[nn][1] + b1v);
                vsm[col * 136 + tok1]       = __float2bfloat16(sacc[nn][2] + b0v);
                vsm[(col + 1) * 136 + tok1] = __float2bfloat16(sacc[nn][3] + b1v);
            }
        }
    }
    __syncthreads();

    // ---- V copy-out: vsm [d][tok] -> g_vtb vectorized ----------------------
    {
        int d = tid >> 2, seg = tid & 3;
        const float4* src = (const float4*)(vsm + d * 136 + seg * 32);
        float4* dst = (float4*)(g_vtb + ((size_t)b * 64 + d) * 4096 + tile * 128 + seg * 32);
        dst[0] = src[0]; dst[1] = src[1]; dst[2] = src[2]; dst[3] = src[3];
    }
}

// ---------------- kernel 2: split-K flash attention (partials) --------------
// Grid 128 = b(4) x qt(16) x half(2). CTA: 256 threads = 8 warps, 256 queries
// (32/warp, two 16-row subtiles sharing every B fragment), 2048 keys.
#define SSTR 72                    // smem row stride in bf16 (144B)
#define KVB  (64 * SSTR * 2)       // bytes per tile stage

__global__ void __launch_bounds__(256, 1) attn_kernel()
{
    extern __shared__ __align__(16) __nv_bfloat16 dsm[];
    __nv_bfloat16* Qs  = dsm;                   // 256 x SSTR
    __nv_bfloat16* Ks  = Qs + 256 * SSTR;       // 3 stages x 64 x SSTR
    __nv_bfloat16* Vts = Ks + 3 * 64 * SSTR;    // 3 stages x 64 x SSTR

    int bx = blockIdx.x;
    int b = bx >> 5, rem = bx & 31;
    int qt = rem >> 1, half = rem & 1;
    int t0 = qt * 256, kt0 = half * 32;
    int tid = threadIdx.x, warp = tid >> 5, lane = tid & 31;
    int qr = warp * 32;
    int g = lane >> 2, c4 = lane & 3;

    const __nv_bfloat16* qg  = g_qb  + ((size_t)b * 4096 + t0) * 64;
    const __nv_bfloat16* kgb = g_kb  + ((size_t)b * 4096 + kt0 * 64) * 64;
    const __nv_bfloat16* vtg = g_vtb + (size_t)b * 64 * 4096 + kt0 * 64;

    unsigned qbase = (unsigned)__cvta_generic_to_shared(Qs);
    unsigned kbase = (unsigned)__cvta_generic_to_shared(Ks);
    unsigned vbase = (unsigned)__cvta_generic_to_shared(Vts);

    int lrow0 = tid >> 3, lrow1 = lrow0 + 32, lcc = tid & 7;
    unsigned o0 = (unsigned)((lrow0 * SSTR + lcc * 8) * 2);
    unsigned o1 = (unsigned)((lrow1 * SSTR + lcc * 8) * 2);
    const __nv_bfloat16* ksrc0 = kgb + lrow0 * 64 + lcc * 8;
    const __nv_bfloat16* ksrc1 = kgb + lrow1 * 64 + lcc * 8;
    const __nv_bfloat16* vsrc0 = vtg + (size_t)lrow0 * 4096 + lcc * 8;
    const __nv_bfloat16* vsrc1 = vtg + (size_t)lrow1 * 4096 + lcc * 8;

    #pragma unroll
    for (int j = 0; j < 8; j++) {
        int i = tid + j * 256, row = i >> 3, cc = i & 7;
        CP_ASYNC16(qbase + (unsigned)((row * SSTR + cc * 8) * 2),
                   qg + row * 64 + cc * 8);
    }
    CP_ASYNC16(kbase + o0, ksrc0);
    CP_ASYNC16(kbase + o1, ksrc1);
    CP_ASYNC16(vbase + o0, vsrc0);
    CP_ASYNC16(vbase + o1, vsrc1);
    CP_COMMIT();   // G0
    CP_ASYNC16(kbase + KVB + o0, ksrc0 + 64 * 64);
    CP_ASYNC16(kbase + KVB + o1, ksrc1 + 64 * 64);
    CP_ASYNC16(vbase + KVB + o0, vsrc0 + 64);
    CP_ASYNC16(vbase + KVB + o1, vsrc1 + 64);
    CP_COMMIT();   // G1

    CP_WAIT1();
    __syncthreads();

    int arow = (lane & 7) + (lane & 8);
    int acol = (lane >> 4) << 3;
    unsigned aaddr0 = qbase + (unsigned)(((qr + arow) * SSTR + acol) * 2);
    unsigned aaddr1 = qbase + (unsigned)(((qr + 16 + arow) * SSTR + acol) * 2);
    unsigned aQ0[4][4], aQ1[4][4];
    #pragma unroll
    for (int kk = 0; kk < 4; kk++) {
        LDSM4(aQ0[kk][0], aQ0[kk][1], aQ0[kk][2], aQ0[kk][3], aaddr0 + kk * 32);
        LDSM4(aQ1[kk][0], aQ1[kk][1], aQ1[kk][2], aQ1[kk][3], aaddr1 + kk * 32);
    }

    unsigned boff = (unsigned)((((lane & 7) + ((lane & 16) >> 1)) * SSTR + (lane & 8)) * 2);

    float of0[8][4], of1[8][4];
    #pragma unroll
    for (int nn = 0; nn < 8; nn++)
        #pragma unroll
        for (int i = 0; i < 4; i++) { of0[nn][i] = 0.f; of1[nn][i] = 0.f; }
    float l00 = 0.f, l01 = 0.f, l10 = 0.f, l11 = 0.f;

    int stc = 0;
    for (int t = 0; t < 32; t++) {
        CP_WAIT1();
        __syncthreads();

        if (t + 2 < 32) {
            unsigned st = (unsigned)((t + 2) % 3) * KVB;
            const __nv_bfloat16* k0 = ksrc0 + (size_t)(t + 2) * 64 * 64;
            const __nv_bfloat16* k1 = ksrc1 + (size_t)(t + 2) * 64 * 64;
            CP_ASYNC16(kbase + st + o0, k0);
            CP_ASYNC16(kbase + st + o1, k1);
            CP_ASYNC16(vbase + st + o0, vsrc0 + (t + 2) * 64);
            CP_ASYNC16(vbase + st + o1, vsrc1 + (t + 2) * 64);
        }
        CP_COMMIT();

        unsigned kb = kbase + (unsigned)(stc * KVB) + boff;
        unsigned vb = vbase + (unsigned)(stc * KVB) + boff;
        stc = (stc == 2) ? 0 : stc + 1;

        float s0[8][4], s1[8][4];
        #pragma unroll
        for (int nn = 0; nn < 8; nn++)
            #pragma unroll
            for (int i = 0; i < 4; i++) { s0[nn][i] = 0.f; s1[nn][i] = 0.f; }
        #pragma unroll
        for (int kk = 0; kk < 4; kk++) {
            #pragma unroll
            for (int np = 0; np < 4; np++) {
                unsigned b0, b1, b2, b3;
                LDSM4(b0, b1, b2, b3, kb + (unsigned)((np * 16 * SSTR + kk * 16) * 2));
                MMA16816(s0[2 * np],     aQ0[kk][0], aQ0[kk][1], aQ0[kk][2], aQ0[kk][3], b0, b1);
                MMA16816(s0[2 * np + 1], aQ0[kk][0], aQ0[kk][1], aQ0[kk][2], aQ0[kk][3], b2, b3);
                MMA16816(s1[2 * np],     aQ1[kk][0], aQ1[kk][1], aQ1[kk][2], aQ1[kk][3], b0, b1);
                MMA16816(s1[2 * np + 1], aQ1[kk][0], aQ1[kk][1], aQ1[kk][2], aQ1[kk][3], b2, b3);
            }
        }

        #pragma unroll
        for (int nn = 0; nn < 8; nn++) {
            s0[nn][0] = ex2(s0[nn][0]); s0[nn][1] = ex2(s0[nn][1]);
            s0[nn][2] = ex2(s0[nn][2]); s0[nn][3] = ex2(s0[nn][3]);
            l00 += s0[nn][0] + s0[nn][1];
            l01 += s0[nn][2] + s0[nn][3];
            s1[nn][0] = ex2(s1[nn][0]); s1[nn][1] = ex2(s1[nn][1]);
            s1[nn][2] = ex2(s1[nn][2]); s1[nn][3] = ex2(s1[nn][3]);
            l10 += s1[nn][0] + s1[nn][1];
            l11 += s1[nn][2] + s1[nn][3];
        }

        #pragma unroll
        for (int kk = 0; kk < 4; kk++) {
            unsigned a00 = pk2(s0[2 * kk][1],     s0[2 * kk][0]);
            unsigned a01 = pk2(s0[2 * kk][3],     s0[2 * kk][2]);
            unsigned a02 = pk2(s0[2 * kk + 1][1], s0[2 * kk + 1][0]);
            unsigned a03 = pk2(s0[2 * kk + 1][3], s0[2 * kk + 1][2]);
            unsigned a10 = pk2(s1[2 * kk][1],     s1[2 * kk][0]);
            unsigned a11 = pk2(s1[2 * kk][3],     s1[2 * kk][2]);
            unsigned a12 = pk2(s1[2 * kk + 1][1], s1[2 * kk + 1][0]);
            unsigned a13 = pk2(s1[2 * kk + 1][3], s1[2 * kk + 1][2]);
            #pragma unroll
            for (int np = 0; np < 4; np++) {
                unsigned b0, b1, b2, b3;
                LDSM4(b0, b1, b2, b3, vb + (unsigned)((np * 16 * SSTR + kk * 16) * 2));
                MMA16816(of0[2 * np],     a00, a01, a02, a03, b0, b1);
                MMA16816(of0[2 * np + 1], a00, a01, a02, a03, b2, b3);
                MMA16816(of1[2 * np],     a10, a11, a12, a13, b0, b1);
                MMA16816(of1[2 * np + 1], a10, a11, a12, a13, b2, b3);
            }
        }
    }

    #pragma unroll
    for (int off = 1; off <= 2; off <<= 1) {
        l00 += __shfl_xor_sync(0xffffffffu, l00, off);
        l01 += __shfl_xor_sync(0xffffffffu, l01, off);
        l10 += __shfl_xor_sync(0xffffffffu, l10, off);
        l11 += __shfl_xor_sync(0xffffffffu, l11, off);
    }
    int r0g = qr + g, r1g = qr + 8 + g, r2g = qr + 16 + g, r3g = qr + 24 + g;
    if (c4 == 0) {
        float* lp = g_pl + (size_t)half * NTOK + (size_t)b * 4096 + t0;
        lp[r0g] = l00; lp[r1g] = l01; lp[r2g] = l10; lp[r3g] = l11;
    }
    float* po = g_po + (size_t)half * NTOK * 64 + ((size_t)b * 4096 + t0) * 64;
    #pragma unroll
    for (int nn = 0; nn < 8; nn++) {
        int col = nn * 8 + c4 * 2;
        *(float2*)(po + (size_t)r0g * 64 + col) = make_float2(of0[nn][0], of0[nn][1]);
        *(float2*)(po + (size_t)r1g * 64 + col) = make_float2(of0[nn][2], of0[nn][3]);
        *(float2*)(po + (size_t)r2g * 64 + col) = make_float2(of1[nn][0], of1[nn][1]);
        *(float2*)(po + (size_t)r3g * 64 + col) = make_float2(of1[nn][2], of1[nn][3]);
    }
}

// ---------------- kernel 3: combine + Wo + residual -------------------------
__global__ void __launch_bounds__(256) combine_kernel(
    const float* __restrict__ bo, float* __restrict__ out)
{
    __shared__ __align__(16) __nv_bfloat16 Obf[128 * SSTR];
    __shared__ __align__(16) __nv_bfloat16 Wt[64 * SSTR];

    int bx = blockIdx.x;
    int b = bx >> 5, qt = bx & 31;
    int t0 = qt * 128;
    int tid = threadIdx.x, warp = tid >> 5, lane = tid & 31;
    int qr = warp * 16;
    int g = lane >> 2, c4 = lane & 3;

    {
        int row = tid >> 1, colh = (tid & 1) * 32;
        size_t tok = (size_t)b * 4096 + t0 + row;
        float inv = 1.f / (g_pl[tok] + g_pl[NTOK + tok]);
        const float4* p0 = (const float4*)(g_po + tok * 64 + colh);
        const float4* p1 = (const float4*)(g_po + (size_t)NTOK * 64 + tok * 64 + colh);
        unsigned* dst = (unsigned*)(Obf + row * SSTR + colh);
        #pragma unroll
        for (int j = 0; j < 8; j++) {
            float4 a = p0[j], c = p1[j];
            float x0 = (a.x + c.x) * inv, y0 = (a.y + c.y) * inv;
            float z0 = (a.z + c.z) * inv, w0 = (a.w + c.w) * inv;
            dst[j * 2 + 0] = pk2(y0, x0);
            dst[j * 2 + 1] = pk2(w0, z0);
        }
    }
    for (int i = tid; i < 512; i += 256) {
        int row = i >> 3, cc = i & 7;
        *(float4*)(Wt + row * SSTR + cc * 8) =
            *(const float4*)(g_woT + row * 64 + cc * 8);
    }
    __syncthreads();

    unsigned obase = (unsigned)__cvta_generic_to_shared(Obf);
    unsigned wbase = (unsigned)__cvta_generic_to_shared(Wt);
    int arow = (lane & 7) + (lane & 8);
    int acol = (lane >> 4) << 3;
    unsigned aaddr = obase + (unsigned)(((qr + arow) * SSTR + acol) * 2);
    unsigned boff = (unsigned)((((lane & 7) + ((lane & 16) >> 1)) * SSTR + (lane & 8)) * 2);

    float r[8][4];
    #pragma unroll
    for (int nn = 0; nn < 8; nn++)
        #pragma unroll
        for (int i = 0; i < 4; i++) r[nn][i] = 0.f;
    #pragma unroll
    for (int kk = 0; kk < 4; kk++) {
        unsigned a0, a1, a2, a3;
        LDSM4(a0, a1, a2, a3, aaddr + kk * 32);
        #pragma unroll
        for (int np = 0; np < 4; np++) {
            unsigned b0, b1, b2, b3;
            LDSM4(b0, b1, b2, b3, wbase + boff + (unsigned)((np * 16 * SSTR + kk * 16) * 2));
            MMA16816(r[2 * np],     a0, a1, a2, a3, b0, b1);
            MMA16816(r[2 * np + 1], a0, a1, a2, a3, b2, b3);
        }
    }

    #pragma unroll
    for (int nn = 0; nn < 8; nn++) {
        int col = nn * 8 + c4 * 2;
        float2 bv = *(const float2*)(bo + col);
        size_t i0 = ((size_t)b * 4096 + t0 + qr + g) * 64 + col;
        float2 x0 = *(const float2*)(g_xn + i0);
        *(float2*)(out + i0) = make_float2(r[nn][0] + bv.x + x0.x,
                                           r[nn][1] + bv.y + x0.y);
        size_t i1 = i0 + (size_t)8 * 64;
        float2 x1 = *(const float2*)(g_xn + i1);
        *(float2*)(out + i1) = make_float2(r[nn][2] + bv.x + x1.x,
                                           r[nn][3] + bv.y + x1.y);
    }
}

// ---------------- launch ----------------------------------------------------
extern "C" void kernel_launch(void* const* d_in, const int* in_sizes, int n_in,
                              void* d_out, int out_size)
{
    const float* x     = (const float*)d_in[0];
    const float* gamma = (const float*)d_in[1];
    const float* beta  = (const float*)d_in[2];
    const float* Wq    = (const float*)d_in[3];
    const float* bq    = (const float*)d_in[4];
    const float* Wk    = (const float*)d_in[5];
    const float* bk    = (const float*)d_in[6];
    const float* Wv    = (const float*)d_in[7];
    const float* bv    = (const float*)d_in[8];
    const float* Wo    = (const float*)d_in[9];
    const float* bo    = (const float*)d_in[10];
    float* out = (float*)d_out;

    const int attn_smem = (256 * SSTR + 6 * 64 * SSTR) * 2;   // 92160 B
    cudaFuncSetAttribute(attn_kernel,
                         cudaFuncAttributeMaxDynamicSharedMemorySize, attn_smem);
    cudaFuncSetAttribute(gn_qkv_kernel,
                         cudaFuncAttributeMaxDynamicSharedMemorySize, QK_SMEM);

    wprep_kernel<<<16, 1024>>>(Wq, Wk, Wv, Wo);          // FIX: full coverage
    gn_qkv_kernel<<<BATCH * 32, 256, QK_SMEM>>>(x, gamma, beta, bq, bk, bv);
    attn_kernel<<<128, 256, attn_smem>>>();
    combine_kernel<<<128, 256>>>(bo, out);
}